// round 1
// baseline (speedup 1.0000x reference)
#include <cuda_runtime.h>
#include <math.h>

// ---------------- problem constants ----------------
#define BATCH     32
#define HDIM      64          // image H
#define WDIM      64          // image W
#define CDIM      256
#define NHEADS    8
#define HEADD     32
#define WS        8
#define SS        4
#define NWIN      64          // windows per image (8x8)
#define NTOK      64          // tokens per window
#define BWIN      (BATCH*NWIN)        // 2048 total windows
#define ROWS      (BATCH*HDIM*WDIM)   // 131072 rows
#define HIDDEN    1024
#define CPBH      512

// ---------------- scratch (device globals, no alloc) ----------------
__device__ float g_qkv[3u*2048u*8u*64u*32u];        // [s][win][head][n][d]
__device__ float g_attn_out[(size_t)131072*256];    // gathered (B_,N,C)
__device__ float g_proj[(size_t)131072*256];        // gathered
__device__ float g_x1[(size_t)131072*256];          // natural order
__device__ float g_hid[(size_t)131072*1024];        // natural order
__device__ float g_h2[(size_t)131072*256];          // natural order
__device__ float g_bias_table[225*8];
__device__ float g_rpb[8*64*64];
__device__ int   g_gather[131072];

// ---------------- helpers ----------------
__device__ __forceinline__ float gelu_t(float x){
    float x3 = x*x*x;
    float t  = tanhf(0.7978845608028654f * (x + 0.044715f*x3));
    return 0.5f * x * (1.0f + t);
}
__device__ __forceinline__ float warp_sum(float v){
#pragma unroll
    for (int o = 16; o > 0; o >>= 1) v += __shfl_xor_sync(0xffffffffu, v, o);
    return v;
}

// ---------------- setup: gather index (shift + window partition) ----------------
__global__ void k_gather_init(){
    int r = blockIdx.x * 256 + threadIdx.x;
    if (r >= ROWS) return;
    int b_  = r >> 6;          // window index (global)
    int n   = r & 63;          // token within window
    int b   = b_ >> 6;         // batch
    int wid = b_ & 63;         // window within image
    int wh = wid >> 3, ww = wid & 7;
    int i = n >> 3, j = n & 7;
    int h = (wh*8 + i + SS) & 63;   // un-shift (roll by -SS on read)
    int w = (ww*8 + j + SS) & 63;
    g_gather[r] = b*(HDIM*WDIM) + h*WDIM + w;
}

// ---------------- CPB MLP: (225,2) -> relu -> (225,8) ----------------
__device__ __forceinline__ float cpb_coord(int c){
    float t = (float)c * (8.0f/7.0f);
    float v = log2f(fabsf(t) + 1.0f) * (1.0f/3.0f);  // /log2(8)
    return t < 0.f ? -v : v;
}
__global__ void k_cpb(const float* __restrict__ w1, const float* __restrict__ b1,
                      const float* __restrict__ w2){
    int p = threadIdx.x;
    if (p >= 225) return;
    float t0 = cpb_coord(p/15 - 7);
    float t1 = cpb_coord(p%15 - 7);
    float out[8];
#pragma unroll
    for (int h = 0; h < 8; h++) out[h] = 0.f;
    for (int j = 0; j < CPBH; j++){
        float hdn = fmaxf(t0*w1[j] + t1*w1[CPBH + j] + b1[j], 0.f);
#pragma unroll
        for (int h = 0; h < 8; h++) out[h] = fmaf(hdn, w2[j*8 + h], out[h]);
    }
#pragma unroll
    for (int h = 0; h < 8; h++) g_bias_table[p*8 + h] = out[h];
}

// ---------------- rpb = 16*sigmoid(table[rpe_index]) ----------------
__global__ void k_rpb(){
    int idx = blockIdx.x * 256 + threadIdx.x;   // 8*64*64 = 32768
    if (idx >= 8*64*64) return;
    int h = idx >> 12;
    int n = (idx >> 6) & 63;
    int m = idx & 63;
    int dh = (n>>3) - (m>>3) + 7;
    int dw = (n&7)  - (m&7)  + 7;
    float b = g_bias_table[(dh*15 + dw)*8 + h];
    g_rpb[idx] = 16.0f / (1.0f + expf(-b));
}

// ---------------- QKV GEMM with row gather + head scatter ----------------
__global__ __launch_bounds__(256, 2) void gemm_qkv(const float* __restrict__ X,
        const float* __restrict__ W, const float* __restrict__ qb,
        const float* __restrict__ vb){
    __shared__ float As[16][128];
    __shared__ float Bs[16][132];
    const int bm = blockIdx.y * 128;
    const int bn = blockIdx.x * 128;
    const int tid = threadIdx.x;
    const int ty = tid >> 4, tx = tid & 15;
    const int Nn = 768, K = 256;

    const int m0 = tid >> 2,            kq0 = (tid & 3) << 2;
    const int m1 = (tid + 256) >> 2,    kq1 = (tid & 3) << 2;
    const int src0 = g_gather[bm + m0];
    const int src1 = g_gather[bm + m1];

    float acc[8][8];
#pragma unroll
    for (int i = 0; i < 8; i++)
#pragma unroll
        for (int j = 0; j < 8; j++) acc[i][j] = 0.f;

    for (int k0 = 0; k0 < K; k0 += 16){
        {
            float4 a = *(const float4*)(X + (size_t)src0*CDIM + k0 + kq0);
            As[kq0+0][m0]=a.x; As[kq0+1][m0]=a.y; As[kq0+2][m0]=a.z; As[kq0+3][m0]=a.w;
            float4 b = *(const float4*)(X + (size_t)src1*CDIM + k0 + kq1);
            As[kq1+0][m1]=b.x; As[kq1+1][m1]=b.y; As[kq1+2][m1]=b.z; As[kq1+3][m1]=b.w;
        }
#pragma unroll
        for (int l = 0; l < 2; l++){
            int idx = tid + l*256;
            int kk = idx >> 5, nn = (idx & 31) << 2;
            float4 b = *(const float4*)(W + (size_t)(k0+kk)*Nn + bn + nn);
            *(float4*)(&Bs[kk][nn]) = b;
        }
        __syncthreads();
#pragma unroll
        for (int kk = 0; kk < 16; kk++){
            float ar[8], br[8];
#pragma unroll
            for (int i = 0; i < 8; i++) ar[i] = As[kk][ty*8 + i];
#pragma unroll
            for (int j = 0; j < 8; j++) br[j] = Bs[kk][tx*8 + j];
#pragma unroll
            for (int i = 0; i < 8; i++)
#pragma unroll
                for (int j = 0; j < 8; j++)
                    acc[i][j] = fmaf(ar[i], br[j], acc[i][j]);
        }
        __syncthreads();
    }
#pragma unroll
    for (int i = 0; i < 8; i++){
        int r  = bm + ty*8 + i;
        int b_ = r >> 6, n = r & 63;
#pragma unroll
        for (int j = 0; j < 8; j++){
            int c = bn + tx*8 + j;
            int s2 = c >> 8; int rem = c & 255;
            int h = rem >> 5; int d = rem & 31;
            float bias = (s2 == 0) ? qb[rem] : ((s2 == 2) ? vb[rem] : 0.f);
            size_t off = ((size_t)(s2*BWIN + b_)*NHEADS + h)*(64*32) + n*32 + d;
            g_qkv[off] = acc[i][j] + bias;
        }
    }
}

// ---------------- generic 128x128 SGEMM, row-major, +bias, optional GELU ----------------
template<int ACT>
__global__ __launch_bounds__(256, 2) void gemm_k(const float* __restrict__ A,
        const float* __restrict__ B, const float* __restrict__ bias,
        float* __restrict__ C, int K, int Nn){
    __shared__ float As[16][128];
    __shared__ float Bs[16][132];
    const int bm = blockIdx.y * 128;
    const int bn = blockIdx.x * 128;
    const int tid = threadIdx.x;
    const int ty = tid >> 4, tx = tid & 15;

    float acc[8][8];
#pragma unroll
    for (int i = 0; i < 8; i++)
#pragma unroll
        for (int j = 0; j < 8; j++) acc[i][j] = 0.f;

    for (int k0 = 0; k0 < K; k0 += 16){
#pragma unroll
        for (int l = 0; l < 2; l++){
            int idx = tid + l*256;
            int m = idx >> 2, kq = (idx & 3) << 2;
            float4 a = *(const float4*)(A + (size_t)(bm+m)*K + k0 + kq);
            As[kq+0][m]=a.x; As[kq+1][m]=a.y; As[kq+2][m]=a.z; As[kq+3][m]=a.w;
        }
#pragma unroll
        for (int l = 0; l < 2; l++){
            int idx = tid + l*256;
            int kk = idx >> 5, nn = (idx & 31) << 2;
            float4 b = *(const float4*)(B + (size_t)(k0+kk)*Nn + bn + nn);
            *(float4*)(&Bs[kk][nn]) = b;
        }
        __syncthreads();
#pragma unroll
        for (int kk = 0; kk < 16; kk++){
            float ar[8], br[8];
#pragma unroll
            for (int i = 0; i < 8; i++) ar[i] = As[kk][ty*8 + i];
#pragma unroll
            for (int j = 0; j < 8; j++) br[j] = Bs[kk][tx*8 + j];
#pragma unroll
            for (int i = 0; i < 8; i++)
#pragma unroll
                for (int j = 0; j < 8; j++)
                    acc[i][j] = fmaf(ar[i], br[j], acc[i][j]);
        }
        __syncthreads();
    }
#pragma unroll
    for (int i = 0; i < 8; i++){
        float* crow = C + (size_t)(bm + ty*8 + i)*Nn + bn;
#pragma unroll
        for (int j = 0; j < 8; j++){
            int c = tx*8 + j;
            float v = acc[i][j] + bias[bn + c];
            if (ACT == 1) v = gelu_t(v);
            crow[c] = v;
        }
    }
}

// ---------------- attention: one (window, head) per block ----------------
__global__ __launch_bounds__(64) void k_attn(const float* __restrict__ ls){
    const int b_ = blockIdx.x;
    const int hh = blockIdx.y;
    const int n  = threadIdx.x;
    __shared__ float kn[64][32];
    __shared__ float vs[64][32];
    __shared__ int   rg[64];

    const size_t sstride = (size_t)BWIN * NHEADS * 64 * 32;   // per q/k/v
    const size_t base = ((size_t)b_*NHEADS + hh)*(64*32) + n*32;
    const float* qp = g_qkv + base;
    const float* kp = g_qkv + sstride + base;
    const float* vp = g_qkv + 2*sstride + base;

    float qr[32]; float s = 0.f;
#pragma unroll
    for (int d = 0; d < 32; d++){ qr[d] = qp[d]; s = fmaf(qr[d], qr[d], s); }
    float qi = rsqrtf(fmaxf(s, 1e-12f));
#pragma unroll
    for (int d = 0; d < 32; d++) qr[d] *= qi;

    s = 0.f; float kr[32];
#pragma unroll
    for (int d = 0; d < 32; d++){ kr[d] = kp[d]; s = fmaf(kr[d], kr[d], s); }
    float ki = rsqrtf(fmaxf(s, 1e-12f));
#pragma unroll
    for (int d = 0; d < 32; d++) kn[n][d] = kr[d]*ki;
#pragma unroll
    for (int d = 0; d < 32; d++) vs[n][d] = vp[d];

    int wid = b_ & 63;
    int gh = (wid >> 3)*8 + (n >> 3);
    int gw = (wid & 7)*8 + (n & 7);
    int hr = gh < 56 ? 0 : (gh < 60 ? 1 : 2);
    int wr = gw < 56 ? 0 : (gw < 60 ? 1 : 2);
    rg[n] = hr*3 + wr;
    __syncthreads();

    float scale = expf(fminf(ls[hh], 4.6051701859880914f));  // ln(100)
    const float* rp = g_rpb + (hh*64 + n)*64;
    int myreg = hr*3 + wr;

    float logits[64];
    float mx = -3.0e38f;
    for (int m = 0; m < 64; m++){
        float dot = 0.f;
#pragma unroll
        for (int d = 0; d < 32; d++) dot = fmaf(qr[d], kn[m][d], dot);
        float lg = fmaf(dot, scale, rp[m]);
        if (rg[m] != myreg) lg -= 100.f;
        logits[m] = lg;
        mx = fmaxf(mx, lg);
    }
    float sum = 0.f;
    for (int m = 0; m < 64; m++){
        float p = expf(logits[m] - mx);
        logits[m] = p;
        sum += p;
    }
    float inv = 1.f / sum;

    float acc[32];
#pragma unroll
    for (int d = 0; d < 32; d++) acc[d] = 0.f;
    for (int m = 0; m < 64; m++){
        float p = logits[m];
#pragma unroll
        for (int d = 0; d < 32; d++) acc[d] = fmaf(p, vs[m][d], acc[d]);
    }
    float* op = g_attn_out + ((size_t)b_*64 + n)*CDIM + hh*32;
#pragma unroll
    for (int d = 0; d < 32; d++) op[d] = acc[d]*inv;
}

// ---------------- LN1 + residual, scatter back (window reverse + unshift) ----------------
__global__ void k_ln1(const float* __restrict__ x, const float* __restrict__ sc,
                      const float* __restrict__ bi){
    int r    = blockIdx.x*8 + (threadIdx.x >> 5);
    int lane = threadIdx.x & 31;
    const float* row = g_proj + (size_t)r*CDIM;
    float v[8]; float s = 0.f;
#pragma unroll
    for (int t = 0; t < 8; t++){ v[t] = row[lane + t*32]; s += v[t]; }
    s = warp_sum(s);
    float mu = s * (1.f/256.f);
    float var = 0.f;
#pragma unroll
    for (int t = 0; t < 8; t++){ float d = v[t]-mu; var = fmaf(d, d, var); }
    var = warp_sum(var) * (1.f/256.f);
    float invs = rsqrtf(var + 1e-6f);
    int dst = g_gather[r];
    const float* xr = x + (size_t)dst*CDIM;
    float* o = g_x1 + (size_t)dst*CDIM;
#pragma unroll
    for (int t = 0; t < 8; t++){
        int c = lane + t*32;
        o[c] = xr[c] + (v[t]-mu)*invs*sc[c] + bi[c];
    }
}

// ---------------- LN2 + residual -> d_out ----------------
__global__ void k_ln2(const float* __restrict__ sc, const float* __restrict__ bi,
                      float* __restrict__ out){
    int r    = blockIdx.x*8 + (threadIdx.x >> 5);
    int lane = threadIdx.x & 31;
    const float* row = g_h2 + (size_t)r*CDIM;
    float v[8]; float s = 0.f;
#pragma unroll
    for (int t = 0; t < 8; t++){ v[t] = row[lane + t*32]; s += v[t]; }
    s = warp_sum(s);
    float mu = s * (1.f/256.f);
    float var = 0.f;
#pragma unroll
    for (int t = 0; t < 8; t++){ float d = v[t]-mu; var = fmaf(d, d, var); }
    var = warp_sum(var) * (1.f/256.f);
    float invs = rsqrtf(var + 1e-6f);
    const float* x1r = g_x1 + (size_t)r*CDIM;
    float* o = out + (size_t)r*CDIM;
#pragma unroll
    for (int t = 0; t < 8; t++){
        int c = lane + t*32;
        o[c] = x1r[c] + (v[t]-mu)*invs*sc[c] + bi[c];
    }
}

// ---------------- launch ----------------
extern "C" void kernel_launch(void* const* d_in, const int* in_sizes, int n_in,
                              void* d_out, int out_size){
    const float* x      = (const float*)d_in[0];
    const float* qkv_w  = (const float*)d_in[1];
    const float* q_bias = (const float*)d_in[2];
    const float* v_bias = (const float*)d_in[3];
    const float* lscale = (const float*)d_in[4];
    const float* cpb_w1 = (const float*)d_in[5];
    const float* cpb_b1 = (const float*)d_in[6];
    const float* cpb_w2 = (const float*)d_in[7];
    const float* proj_w = (const float*)d_in[8];
    const float* proj_b = (const float*)d_in[9];
    const float* n1s    = (const float*)d_in[10];
    const float* n1b    = (const float*)d_in[11];
    const float* n2s    = (const float*)d_in[12];
    const float* n2b    = (const float*)d_in[13];
    const float* fc1_w  = (const float*)d_in[14];
    const float* fc1_b  = (const float*)d_in[15];
    const float* fc2_w  = (const float*)d_in[16];
    const float* fc2_b  = (const float*)d_in[17];
    float* out = (float*)d_out;

    void *p_attn, *p_proj, *p_x1, *p_hid, *p_h2;
    cudaGetSymbolAddress(&p_attn, g_attn_out);
    cudaGetSymbolAddress(&p_proj, g_proj);
    cudaGetSymbolAddress(&p_x1,   g_x1);
    cudaGetSymbolAddress(&p_hid,  g_hid);
    cudaGetSymbolAddress(&p_h2,   g_h2);

    k_gather_init<<<ROWS/256, 256>>>();
    k_cpb<<<1, 256>>>(cpb_w1, cpb_b1, cpb_w2);
    k_rpb<<<(8*64*64)/256, 256>>>();

    // QKV: (131072 x 256) @ (256 x 768), gathered rows, scattered heads
    gemm_qkv<<<dim3(768/128, ROWS/128), 256>>>(x, qkv_w, q_bias, v_bias);

    // attention: one block per (window, head)
    k_attn<<<dim3(BWIN, NHEADS), 64>>>(lscale);

    // proj: (131072 x 256) @ (256 x 256)
    gemm_k<0><<<dim3(256/128, ROWS/128), 256>>>((const float*)p_attn, proj_w, proj_b,
                                                (float*)p_proj, 256, 256);
    // LN1 + residual + scatter
    k_ln1<<<ROWS/8, 256>>>(x, n1s, n1b);

    // FC1 + GELU: (131072 x 256) @ (256 x 1024)
    gemm_k<1><<<dim3(1024/128, ROWS/128), 256>>>((const float*)p_x1, fc1_w, fc1_b,
                                                 (float*)p_hid, 256, 1024);
    // FC2: (131072 x 1024) @ (1024 x 256)
    gemm_k<0><<<dim3(256/128, ROWS/128), 256>>>((const float*)p_hid, fc2_w, fc2_b,
                                                (float*)p_h2, 1024, 256);
    // LN2 + residual -> out
    k_ln2<<<ROWS/8, 256>>>(n2s, n2b, out);
}

// round 2
// speedup vs baseline: 2.2385x; 2.2385x over previous
#include <cuda_runtime.h>
#include <math.h>

// ---------------- problem constants ----------------
#define BATCH     32
#define HDIM      64
#define WDIM      64
#define CDIM      256
#define NHEADS    8
#define HEADD     32
#define WS        8
#define SS        4
#define NWIN      64
#define NTOK      64
#define BWIN      (BATCH*NWIN)        // 2048
#define ROWS      (BATCH*HDIM*WDIM)   // 131072
#define HIDDEN    1024
#define CPBH      512

// GEMM tiling
#define BM 128
#define BN 128
#define BK 32
#define PA 36     // A smem row pad (uints): bank = (4*m + k) % 32 -> conflict-free frags
#define PB 136    // B smem row pad (uints): bank = (8*k + n) % 32 -> conflict-free frags

// ---------------- scratch (device globals, no alloc) ----------------
__device__ float g_qkv[3u*2048u*8u*64u*32u];
__device__ float g_attn_out[(size_t)131072*256];
__device__ float g_proj[(size_t)131072*256];
__device__ float g_x1[(size_t)131072*256];
__device__ float g_hid[(size_t)131072*1024];
__device__ float g_h2[(size_t)131072*256];
__device__ float g_bias_table[225*8];
__device__ float g_rpb[8*64*64];
__device__ int   g_gather[131072];

// ---------------- helpers ----------------
__device__ __forceinline__ float gelu_t(float x){
    float x3 = x*x*x;
    float t  = tanhf(0.7978845608028654f * (x + 0.044715f*x3));
    return 0.5f * x * (1.0f + t);
}
__device__ __forceinline__ float warp_sum(float v){
#pragma unroll
    for (int o = 16; o > 0; o >>= 1) v += __shfl_xor_sync(0xffffffffu, v, o);
    return v;
}
__device__ __forceinline__ unsigned f2tf(float f){
    unsigned u; asm("cvt.rna.tf32.f32 %0, %1;" : "=r"(u) : "f"(f)); return u;
}
__device__ __forceinline__ void mma_tf32(float* c, const unsigned* a, const unsigned* b){
    asm volatile("mma.sync.aligned.m16n8k8.row.col.f32.tf32.tf32.f32 "
      "{%0,%1,%2,%3}, {%4,%5,%6,%7}, {%8,%9}, {%0,%1,%2,%3};\n"
      : "+f"(c[0]), "+f"(c[1]), "+f"(c[2]), "+f"(c[3])
      : "r"(a[0]), "r"(a[1]), "r"(a[2]), "r"(a[3]), "r"(b[0]), "r"(b[1]));
}

// ---------------- setup: gather index (shift + window partition) ----------------
__global__ void k_gather_init(){
    int r = blockIdx.x * 256 + threadIdx.x;
    if (r >= ROWS) return;
    int b_  = r >> 6;
    int n   = r & 63;
    int b   = b_ >> 6;
    int wid = b_ & 63;
    int wh = wid >> 3, ww = wid & 7;
    int i = n >> 3, j = n & 7;
    int h = (wh*8 + i + SS) & 63;
    int w = (ww*8 + j + SS) & 63;
    g_gather[r] = b*(HDIM*WDIM) + h*WDIM + w;
}

// ---------------- CPB MLP ----------------
__device__ __forceinline__ float cpb_coord(int c){
    float t = (float)c * (8.0f/7.0f);
    float v = log2f(fabsf(t) + 1.0f) * (1.0f/3.0f);
    return t < 0.f ? -v : v;
}
__global__ void k_cpb(const float* __restrict__ w1, const float* __restrict__ b1,
                      const float* __restrict__ w2){
    int p = threadIdx.x;
    if (p >= 225) return;
    float t0 = cpb_coord(p/15 - 7);
    float t1 = cpb_coord(p%15 - 7);
    float out[8];
#pragma unroll
    for (int h = 0; h < 8; h++) out[h] = 0.f;
    for (int j = 0; j < CPBH; j++){
        float hdn = fmaxf(t0*w1[j] + t1*w1[CPBH + j] + b1[j], 0.f);
#pragma unroll
        for (int h = 0; h < 8; h++) out[h] = fmaf(hdn, w2[j*8 + h], out[h]);
    }
#pragma unroll
    for (int h = 0; h < 8; h++) g_bias_table[p*8 + h] = out[h];
}

__global__ void k_rpb(){
    int idx = blockIdx.x * 256 + threadIdx.x;
    if (idx >= 8*64*64) return;
    int h = idx >> 12;
    int n = (idx >> 6) & 63;
    int m = idx & 63;
    int dh = (n>>3) - (m>>3) + 7;
    int dw = (n&7)  - (m&7)  + 7;
    float b = g_bias_table[(dh*15 + dw)*8 + h];
    g_rpb[idx] = 16.0f / (1.0f + expf(-b));
}

// ============================================================================
// TF32 tensor-core GEMM core. 128x128x32 tile, 256 threads (8 warps, 2Mx4N),
// warp tile 64x32 = 4 mtiles x 4 ntiles of m16n8k8.
// Fragment addressing is conflict-free by pad construction.
// ============================================================================

struct FragState {
    int wm, wn, lr, lc;
    int am, ak, bk, bnc;
};

__device__ __forceinline__ FragState frag_init(){
    FragState s;
    int tid = threadIdx.x;
    int wid = tid >> 5, lane = tid & 31;
    s.wm = (wid >> 2) * 64;     // 0 or 64
    s.wn = (wid & 3) * 32;      // 0,32,64,96
    s.lr = lane >> 2;
    s.lc = lane & 3;
    s.am = tid >> 3;            // A: row 0..31 (+32p), col (tid&7)*4
    s.ak = (tid & 7) * 4;
    s.bk = tid >> 5;            // B: row 0..7 (+8p), col (tid&31)*4
    s.bnc = (tid & 31) * 4;
    return s;
}

// compute over one SMEM-resident k-tile
__device__ __forceinline__ void tile_compute(const unsigned (*As)[PA],
                                             const unsigned (*Bs)[PB],
                                             const FragState& s,
                                             float acc[4][4][4]){
#pragma unroll
    for (int ks = 0; ks < 4; ks++){
        int k = ks*8;
        unsigned af[4][4], bf[4][2];
#pragma unroll
        for (int mt = 0; mt < 4; mt++){
            int r = s.wm + mt*16 + s.lr;
            af[mt][0] = As[r    ][k + s.lc];
            af[mt][1] = As[r + 8][k + s.lc];
            af[mt][2] = As[r    ][k + s.lc + 4];
            af[mt][3] = As[r + 8][k + s.lc + 4];
        }
#pragma unroll
        for (int nt = 0; nt < 4; nt++){
            int c = s.wn + nt*8 + s.lr;
            bf[nt][0] = Bs[k + s.lc    ][c];
            bf[nt][1] = Bs[k + s.lc + 4][c];
        }
#pragma unroll
        for (int mt = 0; mt < 4; mt++)
#pragma unroll
            for (int nt = 0; nt < 4; nt++)
                mma_tf32(acc[mt][nt], af[mt], bf[nt]);
    }
}

// ---------------- generic tf32 GEMM: C = A @ B + bias, optional GELU ----------------
template<int ACT>
__global__ __launch_bounds__(256) void gemm_t(const float* __restrict__ A,
        const float* __restrict__ B, const float* __restrict__ bias,
        float* __restrict__ C, int K, int Nn){
    __shared__ unsigned As[BM][PA];
    __shared__ unsigned Bs[BK][PB];
    const int bm = blockIdx.y * BM;
    const int bn = blockIdx.x * BN;
    FragState s = frag_init();

    float acc[4][4][4];
#pragma unroll
    for (int mt = 0; mt < 4; mt++)
#pragma unroll
        for (int nt = 0; nt < 4; nt++)
#pragma unroll
            for (int q = 0; q < 4; q++) acc[mt][nt][q] = 0.f;

    float4 ra[4], rb[4];
#pragma unroll
    for (int p = 0; p < 4; p++){
        ra[p] = *(const float4*)(A + (size_t)(bm + s.am + 32*p)*K + s.ak);
        rb[p] = *(const float4*)(B + (size_t)(s.bk + 8*p)*Nn + bn + s.bnc);
    }

    for (int k0 = 0; k0 < K; k0 += BK){
        __syncthreads();
#pragma unroll
        for (int p = 0; p < 4; p++){
            unsigned* ap = &As[s.am + 32*p][s.ak];
            ap[0]=f2tf(ra[p].x); ap[1]=f2tf(ra[p].y); ap[2]=f2tf(ra[p].z); ap[3]=f2tf(ra[p].w);
            unsigned* bp = &Bs[s.bk + 8*p][s.bnc];
            bp[0]=f2tf(rb[p].x); bp[1]=f2tf(rb[p].y); bp[2]=f2tf(rb[p].z); bp[3]=f2tf(rb[p].w);
        }
        __syncthreads();
        if (k0 + BK < K){
#pragma unroll
            for (int p = 0; p < 4; p++){
                ra[p] = *(const float4*)(A + (size_t)(bm + s.am + 32*p)*K + k0 + BK + s.ak);
                rb[p] = *(const float4*)(B + (size_t)(k0 + BK + s.bk + 8*p)*Nn + bn + s.bnc);
            }
        }
        tile_compute(As, Bs, s, acc);
    }

#pragma unroll
    for (int mt = 0; mt < 4; mt++){
        int r0 = bm + s.wm + mt*16 + s.lr;
#pragma unroll
        for (int nt = 0; nt < 4; nt++){
            int c0 = bn + s.wn + nt*8 + s.lc*2;
            float b0 = bias[c0], b1 = bias[c0+1];
            float v0 = acc[mt][nt][0] + b0, v1 = acc[mt][nt][1] + b1;
            float v2 = acc[mt][nt][2] + b0, v3 = acc[mt][nt][3] + b1;
            if (ACT == 1){ v0=gelu_t(v0); v1=gelu_t(v1); v2=gelu_t(v2); v3=gelu_t(v3); }
            *(float2*)(C + (size_t)r0*Nn + c0)     = make_float2(v0, v1);
            *(float2*)(C + (size_t)(r0+8)*Nn + c0) = make_float2(v2, v3);
        }
    }
}

// ---------------- QKV tf32 GEMM: gathered A rows, head-scattered output ----------------
__global__ __launch_bounds__(256) void gemm_qkv_t(const float* __restrict__ X,
        const float* __restrict__ W, const float* __restrict__ qb,
        const float* __restrict__ vb){
    __shared__ unsigned As[BM][PA];
    __shared__ unsigned Bs[BK][PB];
    const int bm = blockIdx.y * BM;
    const int bn = blockIdx.x * BN;
    const int K = 256, Nn = 768;
    FragState s = frag_init();

    int src[4];
#pragma unroll
    for (int p = 0; p < 4; p++) src[p] = g_gather[bm + s.am + 32*p];

    float acc[4][4][4];
#pragma unroll
    for (int mt = 0; mt < 4; mt++)
#pragma unroll
        for (int nt = 0; nt < 4; nt++)
#pragma unroll
            for (int q = 0; q < 4; q++) acc[mt][nt][q] = 0.f;

    float4 ra[4], rb[4];
#pragma unroll
    for (int p = 0; p < 4; p++){
        ra[p] = *(const float4*)(X + (size_t)src[p]*K + s.ak);
        rb[p] = *(const float4*)(W + (size_t)(s.bk + 8*p)*Nn + bn + s.bnc);
    }

    for (int k0 = 0; k0 < K; k0 += BK){
        __syncthreads();
#pragma unroll
        for (int p = 0; p < 4; p++){
            unsigned* ap = &As[s.am + 32*p][s.ak];
            ap[0]=f2tf(ra[p].x); ap[1]=f2tf(ra[p].y); ap[2]=f2tf(ra[p].z); ap[3]=f2tf(ra[p].w);
            unsigned* bp = &Bs[s.bk + 8*p][s.bnc];
            bp[0]=f2tf(rb[p].x); bp[1]=f2tf(rb[p].y); bp[2]=f2tf(rb[p].z); bp[3]=f2tf(rb[p].w);
        }
        __syncthreads();
        if (k0 + BK < K){
#pragma unroll
            for (int p = 0; p < 4; p++){
                ra[p] = *(const float4*)(X + (size_t)src[p]*K + k0 + BK + s.ak);
                rb[p] = *(const float4*)(W + (size_t)(k0 + BK + s.bk + 8*p)*Nn + bn + s.bnc);
            }
        }
        tile_compute(As, Bs, s, acc);
    }

    // scatter: value at (r, c) -> g_qkv[s2][b_][h][n][d]
#pragma unroll
    for (int mt = 0; mt < 4; mt++){
#pragma unroll
        for (int nt = 0; nt < 4; nt++){
#pragma unroll
            for (int q = 0; q < 4; q++){
                int r = bm + s.wm + mt*16 + s.lr + ((q >= 2) ? 8 : 0);
                int c = bn + s.wn + nt*8 + s.lc*2 + (q & 1);
                int s2 = c >> 8, rem = c & 255;
                int h = rem >> 5, d = rem & 31;
                float bias = (s2 == 0) ? qb[rem] : ((s2 == 2) ? vb[rem] : 0.f);
                int b_ = r >> 6, n = r & 63;
                size_t off = ((size_t)(s2*BWIN + b_)*NHEADS + h)*(64*32) + n*32 + d;
                g_qkv[off] = acc[mt][nt][q] + bias;
            }
        }
    }
}

// ---------------- attention: one (window, head) per block ----------------
__global__ __launch_bounds__(64) void k_attn(const float* __restrict__ ls){
    const int b_ = blockIdx.x;
    const int hh = blockIdx.y;
    const int n  = threadIdx.x;
    __shared__ float kn[64][32];
    __shared__ float vs[64][32];
    __shared__ int   rg[64];

    const size_t sstride = (size_t)BWIN * NHEADS * 64 * 32;
    const size_t base = ((size_t)b_*NHEADS + hh)*(64*32) + n*32;
    const float* qp = g_qkv + base;
    const float* kp = g_qkv + sstride + base;
    const float* vp = g_qkv + 2*sstride + base;

    float qr[32]; float sacc = 0.f;
#pragma unroll
    for (int d = 0; d < 32; d++){ qr[d] = qp[d]; sacc = fmaf(qr[d], qr[d], sacc); }
    float qi = rsqrtf(fmaxf(sacc, 1e-12f));
#pragma unroll
    for (int d = 0; d < 32; d++) qr[d] *= qi;

    sacc = 0.f; float kr[32];
#pragma unroll
    for (int d = 0; d < 32; d++){ kr[d] = kp[d]; sacc = fmaf(kr[d], kr[d], sacc); }
    float ki = rsqrtf(fmaxf(sacc, 1e-12f));
#pragma unroll
    for (int d = 0; d < 32; d++) kn[n][d] = kr[d]*ki;
#pragma unroll
    for (int d = 0; d < 32; d++) vs[n][d] = vp[d];

    int wid = b_ & 63;
    int gh = (wid >> 3)*8 + (n >> 3);
    int gw = (wid & 7)*8 + (n & 7);
    int hr = gh < 56 ? 0 : (gh < 60 ? 1 : 2);
    int wr = gw < 56 ? 0 : (gw < 60 ? 1 : 2);
    rg[n] = hr*3 + wr;
    __syncthreads();

    float scale = expf(fminf(ls[hh], 4.6051701859880914f));
    const float* rp = g_rpb + (hh*64 + n)*64;
    int myreg = hr*3 + wr;

    float logits[64];
    float mx = -3.0e38f;
    for (int m = 0; m < 64; m++){
        float dot = 0.f;
#pragma unroll
        for (int d = 0; d < 32; d++) dot = fmaf(qr[d], kn[m][d], dot);
        float lg = fmaf(dot, scale, rp[m]);
        if (rg[m] != myreg) lg -= 100.f;
        logits[m] = lg;
        mx = fmaxf(mx, lg);
    }
    float sum = 0.f;
    for (int m = 0; m < 64; m++){
        float p = expf(logits[m] - mx);
        logits[m] = p;
        sum += p;
    }
    float inv = 1.f / sum;

    float acc[32];
#pragma unroll
    for (int d = 0; d < 32; d++) acc[d] = 0.f;
    for (int m = 0; m < 64; m++){
        float p = logits[m];
#pragma unroll
        for (int d = 0; d < 32; d++) acc[d] = fmaf(p, vs[m][d], acc[d]);
    }
    float* op = g_attn_out + ((size_t)b_*64 + n)*CDIM + hh*32;
#pragma unroll
    for (int d = 0; d < 32; d++) op[d] = acc[d]*inv;
}

// ---------------- LN1 + residual, scatter (window reverse + unshift) ----------------
__global__ void k_ln1(const float* __restrict__ x, const float* __restrict__ sc,
                      const float* __restrict__ bi){
    int r    = blockIdx.x*8 + (threadIdx.x >> 5);
    int lane = threadIdx.x & 31;
    const float* row = g_proj + (size_t)r*CDIM;
    float v[8]; float s = 0.f;
#pragma unroll
    for (int t = 0; t < 8; t++){ v[t] = row[lane + t*32]; s += v[t]; }
    s = warp_sum(s);
    float mu = s * (1.f/256.f);
    float var = 0.f;
#pragma unroll
    for (int t = 0; t < 8; t++){ float d = v[t]-mu; var = fmaf(d, d, var); }
    var = warp_sum(var) * (1.f/256.f);
    float invs = rsqrtf(var + 1e-6f);
    int dst = g_gather[r];
    const float* xr = x + (size_t)dst*CDIM;
    float* o = g_x1 + (size_t)dst*CDIM;
#pragma unroll
    for (int t = 0; t < 8; t++){
        int c = lane + t*32;
        o[c] = xr[c] + (v[t]-mu)*invs*sc[c] + bi[c];
    }
}

// ---------------- LN2 + residual -> d_out ----------------
__global__ void k_ln2(const float* __restrict__ sc, const float* __restrict__ bi,
                      float* __restrict__ out){
    int r    = blockIdx.x*8 + (threadIdx.x >> 5);
    int lane = threadIdx.x & 31;
    const float* row = g_h2 + (size_t)r*CDIM;
    float v[8]; float s = 0.f;
#pragma unroll
    for (int t = 0; t < 8; t++){ v[t] = row[lane + t*32]; s += v[t]; }
    s = warp_sum(s);
    float mu = s * (1.f/256.f);
    float var = 0.f;
#pragma unroll
    for (int t = 0; t < 8; t++){ float d = v[t]-mu; var = fmaf(d, d, var); }
    var = warp_sum(var) * (1.f/256.f);
    float invs = rsqrtf(var + 1e-6f);
    const float* x1r = g_x1 + (size_t)r*CDIM;
    float* o = out + (size_t)r*CDIM;
#pragma unroll
    for (int t = 0; t < 8; t++){
        int c = lane + t*32;
        o[c] = x1r[c] + (v[t]-mu)*invs*sc[c] + bi[c];
    }
}

// ---------------- launch ----------------
extern "C" void kernel_launch(void* const* d_in, const int* in_sizes, int n_in,
                              void* d_out, int out_size){
    const float* x      = (const float*)d_in[0];
    const float* qkv_w  = (const float*)d_in[1];
    const float* q_bias = (const float*)d_in[2];
    const float* v_bias = (const float*)d_in[3];
    const float* lscale = (const float*)d_in[4];
    const float* cpb_w1 = (const float*)d_in[5];
    const float* cpb_b1 = (const float*)d_in[6];
    const float* cpb_w2 = (const float*)d_in[7];
    const float* proj_w = (const float*)d_in[8];
    const float* proj_b = (const float*)d_in[9];
    const float* n1s    = (const float*)d_in[10];
    const float* n1b    = (const float*)d_in[11];
    const float* n2s    = (const float*)d_in[12];
    const float* n2b    = (const float*)d_in[13];
    const float* fc1_w  = (const float*)d_in[14];
    const float* fc1_b  = (const float*)d_in[15];
    const float* fc2_w  = (const float*)d_in[16];
    const float* fc2_b  = (const float*)d_in[17];
    float* out = (float*)d_out;

    void *p_attn, *p_proj, *p_x1, *p_hid, *p_h2;
    cudaGetSymbolAddress(&p_attn, g_attn_out);
    cudaGetSymbolAddress(&p_proj, g_proj);
    cudaGetSymbolAddress(&p_x1,   g_x1);
    cudaGetSymbolAddress(&p_hid,  g_hid);
    cudaGetSymbolAddress(&p_h2,   g_h2);

    k_gather_init<<<ROWS/256, 256>>>();
    k_cpb<<<1, 256>>>(cpb_w1, cpb_b1, cpb_w2);
    k_rpb<<<(8*64*64)/256, 256>>>();

    // QKV: (131072 x 256) @ (256 x 768), gathered rows, scattered heads
    gemm_qkv_t<<<dim3(768/BN, ROWS/BM), 256>>>(x, qkv_w, q_bias, v_bias);

    // attention
    k_attn<<<dim3(BWIN, NHEADS), 64>>>(lscale);

    // proj: (131072 x 256) @ (256 x 256)
    gemm_t<0><<<dim3(256/BN, ROWS/BM), 256>>>((const float*)p_attn, proj_w, proj_b,
                                              (float*)p_proj, 256, 256);
    // LN1 + residual + scatter
    k_ln1<<<ROWS/8, 256>>>(x, n1s, n1b);

    // FC1 + GELU: (131072 x 256) @ (256 x 1024)
    gemm_t<1><<<dim3(1024/BN, ROWS/BM), 256>>>((const float*)p_x1, fc1_w, fc1_b,
                                               (float*)p_hid, 256, 1024);
    // FC2: (131072 x 1024) @ (1024 x 256)
    gemm_t<0><<<dim3(256/BN, ROWS/BM), 256>>>((const float*)p_hid, fc2_w, fc2_b,
                                              (float*)p_h2, 1024, 256);
    // LN2 + residual -> out
    k_ln2<<<ROWS/8, 256>>>(n2s, n2b, out);
}